// round 15
// baseline (speedup 1.0000x reference)
#include <cuda_runtime.h>
#include <cuda_bf16.h>
#include <cuda_fp16.h>
#include <cuda_fp8.h>
#include <cstdint>

#define TOKENS 4096
#define DMODEL 2048
#define VOCAB  32000

#define BM 128
#define BN 256
#define BK 128             // fp8 bytes of k per stage
#define NSTAGE 2
#define NTHREADS 256
#define RS 144             // 128 data + 16 pad; conflict-free cp.async & ldmatrix
#define STAGE_A (BM * RS)  // 18432
#define STAGE_B (BN * RS)  // 36864
#define SMEM_BYTES (NSTAGE * (STAGE_A + STAGE_B))   // 110592 -> 2 CTAs/SM

// GEMM split: chunk0 = 37 tile_n cols -> 1184 CTAs = exactly 4 waves of 296
#define TN_SPLIT 37
#define W_ROWS0  (TN_SPLIT * BN)          // 9472 rows
#define W_ROWS1  (VOCAB - W_ROWS0)        // 22528 rows

#define W_SCALE   64.0f
#define INV_SCALE 0.015625f

// ---------------- scratch (no allocs allowed) ----------------
__device__ uint8_t g_xq[(size_t)TOKENS * DMODEL];
__device__ uint8_t g_wq[(size_t)VOCAB * DMODEL];
__device__ float g_rowsum[TOKENS];
__device__ float g_rowtgt[TOKENS];
__device__ int   g_is64;

// ---------------- fused init: zero rowsum + d_out, detect int64 vs int32 ----
__global__ void init_detect_kernel(const int* __restrict__ t, float* __restrict__ out) {
    __shared__ int ok;
    const int tid = threadIdx.x;   // single block, 1024 threads
    if (tid == 0) { ok = 1; }
    __syncthreads();
    for (int i = tid; i < TOKENS / 2; i += blockDim.x)
        if (t[2 * i + 1] != 0) ok = 0;   // benign race: only writes 0
#pragma unroll
    for (int i = tid; i < TOKENS; i += 1024) g_rowsum[i] = 0.f;
    if (tid == 0) out[0] = 0.f;
    __syncthreads();
    if (tid == 0) g_is64 = ok;
}

// ---------------- fp32 -> fp8 e4m3 conversion ----------------
__global__ void cvt_f32_fp8_kernel(const float* __restrict__ in,
                                   uint8_t* __restrict__ out, int n4, float scale) {
    int i = blockIdx.x * blockDim.x + threadIdx.x;
    if (i < n4) {
        float4 v = reinterpret_cast<const float4*>(in)[i];
        __nv_fp8x2_storage_t lo = __nv_cvt_float2_to_fp8x2(
            make_float2(v.x * scale, v.y * scale), __NV_SATFINITE, __NV_E4M3);
        __nv_fp8x2_storage_t hi = __nv_cvt_float2_to_fp8x2(
            make_float2(v.z * scale, v.w * scale), __NV_SATFINITE, __NV_E4M3);
        reinterpret_cast<uint32_t*>(out)[i] = (uint32_t)lo | ((uint32_t)hi << 16);
    }
}

// ---------------- fused FP8 GEMM (f16 acc) + partial log-sum-exp ----------------
// NOTE: mainloop is the R10 schedule, byte-for-byte. It sits exactly at the
// 128-register allocation edge; perturbing instruction order re-introduces
// spills (verified rounds 8, 9, 13). TN0 is a template constant so the split
// adds no kernel parameter and folds into setup-only arithmetic.
template <int TN0>
__global__ __launch_bounds__(NTHREADS, 2)
void gemm_lse_kernel(const int* __restrict__ tgt_i32) {
    extern __shared__ uint8_t smem[];
    uint8_t* As = smem;
    uint8_t* Bs = smem + NSTAGE * STAGE_A;
    __shared__ float rowsum_s[BM];
    __shared__ int   tgt_s[BM];

    const int tid    = threadIdx.x;
    const int lane   = tid & 31;
    const int wid    = tid >> 5;
    const int warp_m = wid >> 2;   // 0..1  (64-row slabs)
    const int warp_n = wid & 3;    // 0..3  (64-col slabs)
    const int g      = lane >> 2;  // 0..7
    const int t4     = lane & 3;
    const int tile_m = blockIdx.x; // fast dim: wave shares B tiles in L2
    const int tile_n = blockIdx.y + TN0;

    const int is64 = g_is64;
    if (tid < BM) {
        int row = tile_m * BM + tid;
        int tv = is64 ? tgt_i32[2 * row] : tgt_i32[row];
        tgt_s[tid]    = tv - tile_n * BN;
        rowsum_s[tid] = 0.f;
    }

    // A x4: mats [m0-7,+0B][m8-15,+0B][m0-7,+16B][m8-15,+16B]
    const uint32_t a_lane_off = (uint32_t)((lane & 15) * RS + (lane >> 4) * 16);
    // B x4: mats [n0-7,+0B][n0-7,+16B][n8-15,+0B][n8-15,+16B]
    const uint32_t b_lane_off = (uint32_t)((((lane >> 4) << 3) + (lane & 7)) * RS +
                                           ((lane >> 3) & 1) * 16);

    const uint32_t As_b = (uint32_t)__cvta_generic_to_shared(As);
    const uint32_t Bs_b = (uint32_t)__cvta_generic_to_shared(Bs);

    // cp.async addressing
    const int rsel = tid >> 3;          // 0..31
    const int csel = (tid & 7) * 16;    // 16B chunk
    const uint8_t* xs = g_xq + (size_t)(tile_m * BM + rsel) * DMODEL + csel;
    const uint8_t* ws = g_wq + (size_t)(tile_n * BN + rsel) * DMODEL + csel;
    const uint32_t dA0 = As_b + rsel * RS + csel;
    const uint32_t dB0 = Bs_b + rsel * RS + csel;
    const uint32_t aB0 = As_b + warp_m * 64 * RS + a_lane_off;
    const uint32_t bB0 = Bs_b + warp_n * 64 * RS + b_lane_off;

    // f16 accumulators: 4*8*2 = 64 regs
    uint32_t acc[4][8][2];
#pragma unroll
    for (int i = 0; i < 4; i++)
#pragma unroll
        for (int j = 0; j < 8; j++) { acc[i][j][0] = 0u; acc[i][j][1] = 0u; }

#define CP16(dst, src)                                                      \
    asm volatile("cp.async.cg.shared.global [%0], [%1], 16;\n"              \
                 :: "r"(dst), "l"(src))
#define LDSMX4(r0, r1, r2, r3, addr)                                        \
    asm volatile("ldmatrix.sync.aligned.m8n8.x4.shared.b16 {%0,%1,%2,%3}, [%4];" \
                 : "=r"(r0), "=r"(r1), "=r"(r2), "=r"(r3) : "r"(addr))

    const int KT = DMODEL / BK;   // 16
    // prologue: stage 0 in one burst
#pragma unroll
    for (int i = 0; i < 4; i++) CP16(dA0 + i * (32 * RS), xs + i * (32 * (size_t)DMODEL));
#pragma unroll
    for (int i = 0; i < 8; i++) CP16(dB0 + i * (32 * RS), ws + i * (32 * (size_t)DMODEL));
    asm volatile("cp.async.commit_group;\n");
    xs += BK; ws += BK;

    int s = 0;
    for (int kt = 0; kt < KT; kt++) {
        asm volatile("cp.async.wait_group 0;\n");
        __syncthreads();

        const uint32_t a_base = s ? aB0 + STAGE_A : aB0;
        const uint32_t b_base = s ? bB0 + STAGE_B : bB0;
        const uint32_t nA = s ? dA0 : dA0 + STAGE_A;   // next-stage dst
        const uint32_t nB = s ? dB0 : dB0 + STAGE_B;
        s ^= 1;
        const bool more = (kt + 1 < KT);

#pragma unroll
        for (int q = 0; q < 4; q++) {              // 32B k-quarters
            uint32_t a[4][4], b[4][4];
#pragma unroll
            for (int mi = 0; mi < 4; mi++)
                LDSMX4(a[mi][0], a[mi][1], a[mi][2], a[mi][3],
                       a_base + mi * (16 * RS) + q * 32);
#pragma unroll
            for (int pr = 0; pr < 4; pr++)
                LDSMX4(b[pr][0], b[pr][1], b[pr][2], b[pr][3],
                       b_base + pr * (16 * RS) + q * 32);
            // spread next-stage cp.async: 3 chunks per quarter, overlapping MMAs
            if (more) {
                if (q == 0) {
                    CP16(nA + 0 * (32 * RS), xs + 0 * (32 * (size_t)DMODEL));
                    CP16(nA + 1 * (32 * RS), xs + 1 * (32 * (size_t)DMODEL));
                    CP16(nA + 2 * (32 * RS), xs + 2 * (32 * (size_t)DMODEL));
                } else if (q == 1) {
                    CP16(nA + 3 * (32 * RS), xs + 3 * (32 * (size_t)DMODEL));
                    CP16(nB + 0 * (32 * RS), ws + 0 * (32 * (size_t)DMODEL));
                    CP16(nB + 1 * (32 * RS), ws + 1 * (32 * (size_t)DMODEL));
                } else if (q == 2) {
                    CP16(nB + 2 * (32 * RS), ws + 2 * (32 * (size_t)DMODEL));
                    CP16(nB + 3 * (32 * RS), ws + 3 * (32 * (size_t)DMODEL));
                    CP16(nB + 4 * (32 * RS), ws + 4 * (32 * (size_t)DMODEL));
                } else {
                    CP16(nB + 5 * (32 * RS), ws + 5 * (32 * (size_t)DMODEL));
                    CP16(nB + 6 * (32 * RS), ws + 6 * (32 * (size_t)DMODEL));
                    CP16(nB + 7 * (32 * RS), ws + 7 * (32 * (size_t)DMODEL));
                }
            }
#pragma unroll
            for (int mi = 0; mi < 4; mi++)
#pragma unroll
                for (int ni = 0; ni < 8; ni++) {
                    const int pr = ni >> 1, hb = (ni & 1) * 2;
                    asm volatile(
                        "mma.sync.aligned.m16n8k32.row.col.f16.e4m3.e4m3.f16 "
                        "{%0,%1}, {%2,%3,%4,%5}, {%6,%7}, {%0,%1};\n"
                        : "+r"(acc[mi][ni][0]), "+r"(acc[mi][ni][1])
                        : "r"(a[mi][0]), "r"(a[mi][1]),
                          "r"(a[mi][2]), "r"(a[mi][3]),
                          "r"(b[pr][hb]), "r"(b[pr][hb + 1]));
                }
        }
        asm volatile("cp.async.commit_group;\n");   // empty commit ok on last
        if (more) { xs += BK; ws += BK; }
    }
    __syncthreads();

    // ---- epilogue: unpack f16, scale + exp + rowsums + target capture ----
#pragma unroll
    for (int mi = 0; mi < 4; mi++) {
        const int r0 = warp_m * 64 + mi * 16 + g;
        const int r1 = r0 + 8;
        const int tg0 = tgt_s[r0], tg1 = tgt_s[r1];
        float s0 = 0.f, s1 = 0.f;
#pragma unroll
        for (int ni = 0; ni < 8; ni++) {
            const int c = warp_n * 64 + ni * 8 + t4 * 2;
            const __half2 h0 = *reinterpret_cast<const __half2*>(&acc[mi][ni][0]);
            const __half2 h1 = *reinterpret_cast<const __half2*>(&acc[mi][ni][1]);
            const float2 f0 = __half22float2(h0);
            const float2 f1 = __half22float2(h1);
            const float v00 = f0.x * INV_SCALE, v01 = f0.y * INV_SCALE;
            const float v10 = f1.x * INV_SCALE, v11 = f1.y * INV_SCALE;
            s0 += __expf(v00) + __expf(v01);
            s1 += __expf(v10) + __expf(v11);
            if (c     == tg0) g_rowtgt[tile_m * BM + r0] = v00;
            if (c + 1 == tg0) g_rowtgt[tile_m * BM + r0] = v01;
            if (c     == tg1) g_rowtgt[tile_m * BM + r1] = v10;
            if (c + 1 == tg1) g_rowtgt[tile_m * BM + r1] = v11;
        }
        s0 += __shfl_xor_sync(0xffffffffu, s0, 1);
        s0 += __shfl_xor_sync(0xffffffffu, s0, 2);
        s1 += __shfl_xor_sync(0xffffffffu, s1, 1);
        s1 += __shfl_xor_sync(0xffffffffu, s1, 2);
        if (t4 == 0) {
            atomicAdd(&rowsum_s[r0], s0);
            atomicAdd(&rowsum_s[r1], s1);
        }
    }
    __syncthreads();
    if (tid < BM) atomicAdd(&g_rowsum[tile_m * BM + tid], rowsum_s[tid]);
}

// ---------------- final loss reduction ----------------
__global__ void loss_kernel(float* __restrict__ out) {
    int i = blockIdx.x * blockDim.x + threadIdx.x;
    float v = 0.f;
    if (i < TOKENS) v = logf(g_rowsum[i]) - g_rowtgt[i];
#pragma unroll
    for (int o = 16; o > 0; o >>= 1) v += __shfl_xor_sync(0xffffffffu, v, o);
    __shared__ float ws[32];
    if ((threadIdx.x & 31) == 0) ws[threadIdx.x >> 5] = v;
    __syncthreads();
    if (threadIdx.x < 32) {
        float x = (threadIdx.x < (blockDim.x >> 5)) ? ws[threadIdx.x] : 0.f;
#pragma unroll
        for (int o = 16; o > 0; o >>= 1) x += __shfl_xor_sync(0xffffffffu, x, o);
        if (threadIdx.x == 0) atomicAdd(out, x);
    }
}

// ---------------- launch ----------------
extern "C" void kernel_launch(void* const* d_in, const int* in_sizes, int n_in,
                              void* d_out, int out_size) {
    const float* x = (const float*)d_in[0];
    const float* w = (const float*)d_in[1];
    const int*   t = (const int*)d_in[2];

    // one-time resources (created on the first, non-captured, correctness call)
    static cudaStream_t s1 = nullptr;
    static cudaEvent_t  ev_fork = nullptr, ev_w1 = nullptr;
    if (s1 == nullptr) {
        cudaStreamCreateWithFlags(&s1, cudaStreamNonBlocking);
        cudaEventCreateWithFlags(&ev_fork, cudaEventDisableTiming);
        cudaEventCreateWithFlags(&ev_w1, cudaEventDisableTiming);
        cudaFuncSetAttribute(gemm_lse_kernel<0>,
                             cudaFuncAttributeMaxDynamicSharedMemorySize, SMEM_BYTES);
        cudaFuncSetAttribute(gemm_lse_kernel<TN_SPLIT>,
                             cudaFuncAttributeMaxDynamicSharedMemorySize, SMEM_BYTES);
    }

    void *xq_p, *wq_p;
    cudaGetSymbolAddress(&xq_p, g_xq);
    cudaGetSymbolAddress(&wq_p, g_wq);

    init_detect_kernel<<<1, 1024, 0, 0>>>(t, (float*)d_out);

    const int nx4  = TOKENS * DMODEL / 4;
    const int nw40 = W_ROWS0 * DMODEL / 4;   // 4,849,664
    const int nw41 = W_ROWS1 * DMODEL / 4;   // 11,534,336

    cvt_f32_fp8_kernel<<<(nx4 + 255) / 256, 256, 0, 0>>>(
        x, (uint8_t*)xq_p, nx4, 1.0f);
    // w chunk0 (needed by gemm chunk0) on the main stream
    cvt_f32_fp8_kernel<<<(nw40 + 255) / 256, 256, 0, 0>>>(
        w, (uint8_t*)wq_p, nw40, W_SCALE);

    // fork: w chunk1 converts on s1 while gemm chunk0 runs
    cudaEventRecord(ev_fork, 0);
    cudaStreamWaitEvent(s1, ev_fork, 0);
    cvt_f32_fp8_kernel<<<(nw41 + 255) / 256, 256, 0, s1>>>(
        w + (size_t)W_ROWS0 * DMODEL,
        (uint8_t*)wq_p + (size_t)W_ROWS0 * DMODEL, nw41, W_SCALE);
    cudaEventRecord(ev_w1, s1);

    // gemm chunk0: tile_n [0, 37)  -> 1184 CTAs = exactly 4 waves
    dim3 grid0(TOKENS / BM, TN_SPLIT);
    gemm_lse_kernel<0><<<grid0, NTHREADS, SMEM_BYTES, 0>>>(t);

    // join: gemm chunk1 needs w chunk1
    cudaStreamWaitEvent(0, ev_w1, 0);
    dim3 grid1(TOKENS / BM, (VOCAB / BN) - TN_SPLIT);   // 88 cols
    gemm_lse_kernel<TN_SPLIT><<<grid1, NTHREADS, SMEM_BYTES, 0>>>(t);

    loss_kernel<<<4, 1024, 0, 0>>>((float*)d_out);
}

// round 16
// speedup vs baseline: 1.0227x; 1.0227x over previous
#include <cuda_runtime.h>
#include <cuda_bf16.h>
#include <cuda_fp16.h>
#include <cuda_fp8.h>
#include <cstdint>

#define TOKENS 4096
#define DMODEL 2048
#define VOCAB  32000

#define BM 128
#define BN 256
#define BK 128             // fp8 bytes of k per stage
#define NSTAGE 2
#define NTHREADS 256
#define RS 144             // 128 data + 16 pad; conflict-free cp.async & ldmatrix
#define STAGE_A (BM * RS)  // 18432
#define STAGE_B (BN * RS)  // 36864
#define SMEM_BYTES (NSTAGE * (STAGE_A + STAGE_B))   // 110592 -> 2 CTAs/SM

#define W_SCALE   64.0f
#define INV_SCALE 0.015625f

// cvt geometry: 1024 float4 per block (4 per thread)
#define NX4    (TOKENS * DMODEL / 4)     // 2,097,152 float4
#define NXBLK  (NX4 / 1024)              // 2048 blocks (exact)
#define NW4    ((size_t)VOCAB * DMODEL / 4)  // 16,384,000 float4
#define NWBLK  (NW4 / 1024)              // 16000 blocks (exact)

// ---------------- scratch (no allocs allowed) ----------------
__device__ uint8_t g_xq[(size_t)TOKENS * DMODEL];
__device__ uint8_t g_wq[(size_t)VOCAB * DMODEL];
__device__ float g_rowsum[TOKENS];
__device__ float g_rowtgt[TOKENS];
__device__ int   g_is64;

// ---------------- fused init: zero rowsum + d_out, detect int64 vs int32 ----
__global__ void init_detect_kernel(const int* __restrict__ t, float* __restrict__ out) {
    __shared__ int ok;
    const int tid = threadIdx.x;   // single block, 1024 threads
    if (tid == 0) { ok = 1; }
    __syncthreads();
    for (int i = tid; i < TOKENS / 2; i += blockDim.x)
        if (t[2 * i + 1] != 0) ok = 0;   // benign race: only writes 0
#pragma unroll
    for (int i = tid; i < TOKENS; i += 1024) g_rowsum[i] = 0.f;
    if (tid == 0) out[0] = 0.f;
    __syncthreads();
    if (tid == 0) g_is64 = ok;
}

// ---------------- fused fp32 -> fp8 conversion for x AND w, MLP=4 ----------------
__global__ __launch_bounds__(256)
void cvt_all_kernel(const float* __restrict__ x, const float* __restrict__ w) {
    int b = blockIdx.x;
    const float4* src;
    uint32_t* dst;
    float scale;
    if (b < NXBLK) {
        src = reinterpret_cast<const float4*>(x);
        dst = reinterpret_cast<uint32_t*>(g_xq);
        scale = 1.0f;
    } else {
        b -= NXBLK;
        src = reinterpret_cast<const float4*>(w);
        dst = reinterpret_cast<uint32_t*>(g_wq);
        scale = W_SCALE;
    }
    const size_t base = (size_t)b * 1024 + threadIdx.x;
    // 4 independent, coalesced 16B streaming loads (MLP = 4)
    float4 v0 = __ldcs(&src[base + 0 * 256]);
    float4 v1 = __ldcs(&src[base + 1 * 256]);
    float4 v2 = __ldcs(&src[base + 2 * 256]);
    float4 v3 = __ldcs(&src[base + 3 * 256]);
#define PACK8(v)                                                            \
    ((uint32_t)__nv_cvt_float2_to_fp8x2(make_float2((v).x * scale,          \
                                                    (v).y * scale),         \
                                        __NV_SATFINITE, __NV_E4M3) |        \
     ((uint32_t)__nv_cvt_float2_to_fp8x2(make_float2((v).z * scale,         \
                                                     (v).w * scale),        \
                                         __NV_SATFINITE, __NV_E4M3) << 16))
    dst[base + 0 * 256] = PACK8(v0);
    dst[base + 1 * 256] = PACK8(v1);
    dst[base + 2 * 256] = PACK8(v2);
    dst[base + 3 * 256] = PACK8(v3);
#undef PACK8
}

// ---------------- fused FP8 GEMM (f16 acc) + partial log-sum-exp ----------------
// NOTE: mainloop is the R10 schedule, byte-for-byte. It sits exactly at the
// 128-register allocation edge; perturbing instruction order re-introduces
// spills (verified rounds 8, 9, 13). Do not reorder.
__global__ __launch_bounds__(NTHREADS, 2)
void gemm_lse_kernel(const int* __restrict__ tgt_i32) {
    extern __shared__ uint8_t smem[];
    uint8_t* As = smem;
    uint8_t* Bs = smem + NSTAGE * STAGE_A;
    __shared__ float rowsum_s[BM];
    __shared__ int   tgt_s[BM];

    const int tid    = threadIdx.x;
    const int lane   = tid & 31;
    const int wid    = tid >> 5;
    const int warp_m = wid >> 2;   // 0..1  (64-row slabs)
    const int warp_n = wid & 3;    // 0..3  (64-col slabs)
    const int g      = lane >> 2;  // 0..7
    const int t4     = lane & 3;
    const int tile_m = blockIdx.x; // fast dim: wave shares B tiles in L2
    const int tile_n = blockIdx.y;

    const int is64 = g_is64;
    if (tid < BM) {
        int row = tile_m * BM + tid;
        int tv = is64 ? tgt_i32[2 * row] : tgt_i32[row];
        tgt_s[tid]    = tv - tile_n * BN;
        rowsum_s[tid] = 0.f;
    }

    // A x4: mats [m0-7,+0B][m8-15,+0B][m0-7,+16B][m8-15,+16B]
    const uint32_t a_lane_off = (uint32_t)((lane & 15) * RS + (lane >> 4) * 16);
    // B x4: mats [n0-7,+0B][n0-7,+16B][n8-15,+0B][n8-15,+16B]
    const uint32_t b_lane_off = (uint32_t)((((lane >> 4) << 3) + (lane & 7)) * RS +
                                           ((lane >> 3) & 1) * 16);

    const uint32_t As_b = (uint32_t)__cvta_generic_to_shared(As);
    const uint32_t Bs_b = (uint32_t)__cvta_generic_to_shared(Bs);

    // cp.async addressing
    const int rsel = tid >> 3;          // 0..31
    const int csel = (tid & 7) * 16;    // 16B chunk
    const uint8_t* xs = g_xq + (size_t)(tile_m * BM + rsel) * DMODEL + csel;
    const uint8_t* ws = g_wq + (size_t)(tile_n * BN + rsel) * DMODEL + csel;
    const uint32_t dA0 = As_b + rsel * RS + csel;
    const uint32_t dB0 = Bs_b + rsel * RS + csel;
    const uint32_t aB0 = As_b + warp_m * 64 * RS + a_lane_off;
    const uint32_t bB0 = Bs_b + warp_n * 64 * RS + b_lane_off;

    // f16 accumulators: 4*8*2 = 64 regs
    uint32_t acc[4][8][2];
#pragma unroll
    for (int i = 0; i < 4; i++)
#pragma unroll
        for (int j = 0; j < 8; j++) { acc[i][j][0] = 0u; acc[i][j][1] = 0u; }

#define CP16(dst, src)                                                      \
    asm volatile("cp.async.cg.shared.global [%0], [%1], 16;\n"              \
                 :: "r"(dst), "l"(src))
#define LDSMX4(r0, r1, r2, r3, addr)                                        \
    asm volatile("ldmatrix.sync.aligned.m8n8.x4.shared.b16 {%0,%1,%2,%3}, [%4];" \
                 : "=r"(r0), "=r"(r1), "=r"(r2), "=r"(r3) : "r"(addr))

    const int KT = DMODEL / BK;   // 16
    // prologue: stage 0 in one burst
#pragma unroll
    for (int i = 0; i < 4; i++) CP16(dA0 + i * (32 * RS), xs + i * (32 * (size_t)DMODEL));
#pragma unroll
    for (int i = 0; i < 8; i++) CP16(dB0 + i * (32 * RS), ws + i * (32 * (size_t)DMODEL));
    asm volatile("cp.async.commit_group;\n");
    xs += BK; ws += BK;

    int s = 0;
    for (int kt = 0; kt < KT; kt++) {
        asm volatile("cp.async.wait_group 0;\n");
        __syncthreads();

        const uint32_t a_base = s ? aB0 + STAGE_A : aB0;
        const uint32_t b_base = s ? bB0 + STAGE_B : bB0;
        const uint32_t nA = s ? dA0 : dA0 + STAGE_A;   // next-stage dst
        const uint32_t nB = s ? dB0 : dB0 + STAGE_B;
        s ^= 1;
        const bool more = (kt + 1 < KT);

#pragma unroll
        for (int q = 0; q < 4; q++) {              // 32B k-quarters
            uint32_t a[4][4], b[4][4];
#pragma unroll
            for (int mi = 0; mi < 4; mi++)
                LDSMX4(a[mi][0], a[mi][1], a[mi][2], a[mi][3],
                       a_base + mi * (16 * RS) + q * 32);
#pragma unroll
            for (int pr = 0; pr < 4; pr++)
                LDSMX4(b[pr][0], b[pr][1], b[pr][2], b[pr][3],
                       b_base + pr * (16 * RS) + q * 32);
            // spread next-stage cp.async: 3 chunks per quarter, overlapping MMAs
            if (more) {
                if (q == 0) {
                    CP16(nA + 0 * (32 * RS), xs + 0 * (32 * (size_t)DMODEL));
                    CP16(nA + 1 * (32 * RS), xs + 1 * (32 * (size_t)DMODEL));
                    CP16(nA + 2 * (32 * RS), xs + 2 * (32 * (size_t)DMODEL));
                } else if (q == 1) {
                    CP16(nA + 3 * (32 * RS), xs + 3 * (32 * (size_t)DMODEL));
                    CP16(nB + 0 * (32 * RS), ws + 0 * (32 * (size_t)DMODEL));
                    CP16(nB + 1 * (32 * RS), ws + 1 * (32 * (size_t)DMODEL));
                } else if (q == 2) {
                    CP16(nB + 2 * (32 * RS), ws + 2 * (32 * (size_t)DMODEL));
                    CP16(nB + 3 * (32 * RS), ws + 3 * (32 * (size_t)DMODEL));
                    CP16(nB + 4 * (32 * RS), ws + 4 * (32 * (size_t)DMODEL));
                } else {
                    CP16(nB + 5 * (32 * RS), ws + 5 * (32 * (size_t)DMODEL));
                    CP16(nB + 6 * (32 * RS), ws + 6 * (32 * (size_t)DMODEL));
                    CP16(nB + 7 * (32 * RS), ws + 7 * (32 * (size_t)DMODEL));
                }
            }
#pragma unroll
            for (int mi = 0; mi < 4; mi++)
#pragma unroll
                for (int ni = 0; ni < 8; ni++) {
                    const int pr = ni >> 1, hb = (ni & 1) * 2;
                    asm volatile(
                        "mma.sync.aligned.m16n8k32.row.col.f16.e4m3.e4m3.f16 "
                        "{%0,%1}, {%2,%3,%4,%5}, {%6,%7}, {%0,%1};\n"
                        : "+r"(acc[mi][ni][0]), "+r"(acc[mi][ni][1])
                        : "r"(a[mi][0]), "r"(a[mi][1]),
                          "r"(a[mi][2]), "r"(a[mi][3]),
                          "r"(b[pr][hb]), "r"(b[pr][hb + 1]));
                }
        }
        asm volatile("cp.async.commit_group;\n");   // empty commit ok on last
        if (more) { xs += BK; ws += BK; }
    }
    __syncthreads();

    // ---- epilogue: unpack f16, scale + exp + rowsums + target capture ----
#pragma unroll
    for (int mi = 0; mi < 4; mi++) {
        const int r0 = warp_m * 64 + mi * 16 + g;
        const int r1 = r0 + 8;
        const int tg0 = tgt_s[r0], tg1 = tgt_s[r1];
        float s0 = 0.f, s1 = 0.f;
#pragma unroll
        for (int ni = 0; ni < 8; ni++) {
            const int c = warp_n * 64 + ni * 8 + t4 * 2;
            const __half2 h0 = *reinterpret_cast<const __half2*>(&acc[mi][ni][0]);
            const __half2 h1 = *reinterpret_cast<const __half2*>(&acc[mi][ni][1]);
            const float2 f0 = __half22float2(h0);
            const float2 f1 = __half22float2(h1);
            const float v00 = f0.x * INV_SCALE, v01 = f0.y * INV_SCALE;
            const float v10 = f1.x * INV_SCALE, v11 = f1.y * INV_SCALE;
            s0 += __expf(v00) + __expf(v01);
            s1 += __expf(v10) + __expf(v11);
            if (c     == tg0) g_rowtgt[tile_m * BM + r0] = v00;
            if (c + 1 == tg0) g_rowtgt[tile_m * BM + r0] = v01;
            if (c     == tg1) g_rowtgt[tile_m * BM + r1] = v10;
            if (c + 1 == tg1) g_rowtgt[tile_m * BM + r1] = v11;
        }
        s0 += __shfl_xor_sync(0xffffffffu, s0, 1);
        s0 += __shfl_xor_sync(0xffffffffu, s0, 2);
        s1 += __shfl_xor_sync(0xffffffffu, s1, 1);
        s1 += __shfl_xor_sync(0xffffffffu, s1, 2);
        if (t4 == 0) {
            atomicAdd(&rowsum_s[r0], s0);
            atomicAdd(&rowsum_s[r1], s1);
        }
    }
    __syncthreads();
    if (tid < BM) atomicAdd(&g_rowsum[tile_m * BM + tid], rowsum_s[tid]);
}

// ---------------- final loss reduction ----------------
__global__ void loss_kernel(float* __restrict__ out) {
    int i = blockIdx.x * blockDim.x + threadIdx.x;
    float v = 0.f;
    if (i < TOKENS) v = logf(g_rowsum[i]) - g_rowtgt[i];
#pragma unroll
    for (int o = 16; o > 0; o >>= 1) v += __shfl_xor_sync(0xffffffffu, v, o);
    __shared__ float ws[32];
    if ((threadIdx.x & 31) == 0) ws[threadIdx.x >> 5] = v;
    __syncthreads();
    if (threadIdx.x < 32) {
        float x = (threadIdx.x < (blockDim.x >> 5)) ? ws[threadIdx.x] : 0.f;
#pragma unroll
        for (int o = 16; o > 0; o >>= 1) x += __shfl_xor_sync(0xffffffffu, x, o);
        if (threadIdx.x == 0) atomicAdd(out, x);
    }
}

// ---------------- launch ----------------
extern "C" void kernel_launch(void* const* d_in, const int* in_sizes, int n_in,
                              void* d_out, int out_size) {
    const float* x = (const float*)d_in[0];
    const float* w = (const float*)d_in[1];
    const int*   t = (const int*)d_in[2];

    cudaFuncSetAttribute(gemm_lse_kernel,
                         cudaFuncAttributeMaxDynamicSharedMemorySize, SMEM_BYTES);

    init_detect_kernel<<<1, 1024, 0, 0>>>(t, (float*)d_out);

    cvt_all_kernel<<<NXBLK + NWBLK, 256, 0, 0>>>(x, w);

    dim3 grid(TOKENS / BM, VOCAB / BN);   // (32, 125), tile_m fastest
    gemm_lse_kernel<<<grid, NTHREADS, SMEM_BYTES, 0>>>(t);

    loss_kernel<<<4, 1024, 0, 0>>>((float*)d_out);
}